// round 2
// baseline (speedup 1.0000x reference)
#include <cuda_runtime.h>
#include <math.h>

#define NMAX 25000
#define EMAX 400000
#define HID 128
#define INNER 160
#define MSGF 273
#define FS 273     // f shared row stride (floats)
#define MS 162     // m/m1 shared row stride (floats)
#define EB 64      // edges per block

// ---------------- scratch (device globals; no allocation allowed) ----------------
__device__ float g_vals[(size_t)EMAX * 128];   // per-edge value vectors
__device__ float g_logits[(size_t)EMAX * 8];   // per-edge attention logits
__device__ float g_msgx[(size_t)EMAX * 3];     // per-edge coordinate messages
__device__ float g_hagg[(size_t)NMAX * 128];   // aggregated node features
__device__ int g_deg[NMAX];
__device__ int g_cursor[NMAX];
__device__ int g_start[NMAX + 1];
__device__ int g_eid[EMAX];

// ---------------- helpers ----------------
__device__ __forceinline__ unsigned long long pk2(float a, float b) {
    unsigned long long r;
    asm("mov.b64 %0, {%1, %2};" : "=l"(r) : "r"(__float_as_uint(a)), "r"(__float_as_uint(b)));
    return r;
}
__device__ __forceinline__ void upk2(unsigned long long v, float &a, float &b) {
    unsigned int lo, hi;
    asm("mov.b64 {%0, %1}, %2;" : "=r"(lo), "=r"(hi) : "l"(v));
    a = __uint_as_float(lo); b = __uint_as_float(hi);
}
__device__ __forceinline__ void ffma2(unsigned long long &d, unsigned long long a, unsigned long long b) {
    asm("fma.rn.f32x2 %0, %1, %2, %3;" : "=l"(d) : "l"(a), "l"(b), "l"(d));
}
__device__ __forceinline__ float siluf(float x) { return x / (1.0f + __expf(-x)); }

// ---------------- CSR build ----------------
__global__ void k_zero(int n) {
    int i = blockIdx.x * blockDim.x + threadIdx.x;
    if (i < n) { g_deg[i] = 0; g_cursor[i] = 0; }
}
__global__ void k_deg(const int* __restrict__ dst, int E) {
    int e = blockIdx.x * blockDim.x + threadIdx.x;
    if (e < E) atomicAdd(&g_deg[dst[e]], 1);
}
__global__ void k_scan(int n) {
    __shared__ int sh[1024];
    int carry = 0;
    for (int base = 0; base < n; base += 1024) {
        int i = base + threadIdx.x;
        int x = (i < n) ? g_deg[i] : 0;
        sh[threadIdx.x] = x;
        __syncthreads();
        for (int off = 1; off < 1024; off <<= 1) {
            int v = (threadIdx.x >= off) ? sh[threadIdx.x - off] : 0;
            __syncthreads();
            sh[threadIdx.x] += v;
            __syncthreads();
        }
        if (i < n) g_start[i] = carry + sh[threadIdx.x] - x;
        carry += sh[1023];
        __syncthreads();
    }
    if (threadIdx.x == 0) g_start[n] = carry;
}
__global__ void k_fill(const int* __restrict__ dst, int E) {
    int e = blockIdx.x * blockDim.x + threadIdx.x;
    if (e < E) {
        int d = dst[e];
        int p = atomicAdd(&g_cursor[d], 1);
        g_eid[g_start[d] + p] = e;
    }
}

// ---------------- fused edge kernel ----------------
__global__ void __launch_bounds__(256, 1) k_edge(
    const float* __restrict__ h, const float* __restrict__ coords, const float* __restrict__ a,
    const int* __restrict__ src, const int* __restrict__ dst,
    const float* __restrict__ We1, const float* __restrict__ be1,
    const float* __restrict__ We2, const float* __restrict__ be2,
    const float* __restrict__ Wc, const float* __restrict__ Wv, const float* __restrict__ Wa,
    int E)
{
    extern __shared__ float smem[];
    float* sf    = smem;                  // [EB][FS]
    float* sm1   = sf + EB * FS;          // [EB][MS]
    float* smm   = sm1 + EB * MS;         // [EB][MS]
    float* sdiff = smm + EB * MS;         // [EB][3]

    const int tid = threadIdx.x;
    const int eg = blockIdx.x * EB;
    const int warp = tid >> 5, lane = tid & 31;

    // ---- gather f = [h_src(128), h_dst(128), r^2(1), a(16)] ----
    for (int e = warp; e < EB; e += 8) {
        int ed = eg + e; if (ed > E - 1) ed = E - 1;
        int si = src[ed], di = dst[ed];
        float4 hv = ((const float4*)(h + (size_t)si * 128))[lane];
        int b = e * FS + 4 * lane;
        sf[b] = hv.x; sf[b + 1] = hv.y; sf[b + 2] = hv.z; sf[b + 3] = hv.w;
        hv = ((const float4*)(h + (size_t)di * 128))[lane];
        b += 128;
        sf[b] = hv.x; sf[b + 1] = hv.y; sf[b + 2] = hv.z; sf[b + 3] = hv.w;
        if (lane < 4) {
            float4 av = ((const float4*)(a + (size_t)ed * 16))[lane];
            int c = e * FS + 257 + 4 * lane;
            sf[c] = av.x; sf[c + 1] = av.y; sf[c + 2] = av.z; sf[c + 3] = av.w;
        }
        if (lane == 0) {
            float dx = coords[si * 3 + 0] - coords[di * 3 + 0];
            float dy = coords[si * 3 + 1] - coords[di * 3 + 1];
            float dz = coords[si * 3 + 2] - coords[di * 3 + 2];
            sf[e * FS + 256] = dx * dx + dy * dy + dz * dz;
            sdiff[e * 3 + 0] = dx; sdiff[e * 3 + 1] = dy; sdiff[e * 3 + 2] = dz;
        }
    }
    __syncthreads();

    const int ecg = tid >> 4;     // 0..15 edge group: edges ecg+16*i
    const int jcg = tid & 15;     // 0..15 col group: j pairs 2*jcg + 32*p

    // ---- GEMM1: m1 = silu(f @ We1 + be1), [EB][273] x [273][160] ----
    {
        unsigned long long acc[4][5];
        #pragma unroll
        for (int i = 0; i < 4; i++)
            #pragma unroll
            for (int p = 0; p < 5; p++) acc[i][p] = 0ull;
        const float* fr0 = sf + (ecg +  0) * FS;
        const float* fr1 = sf + (ecg + 16) * FS;
        const float* fr2 = sf + (ecg + 32) * FS;
        const float* fr3 = sf + (ecg + 48) * FS;
        #pragma unroll 2
        for (int k = 0; k < MSGF; k++) {
            unsigned long long fa[4];
            fa[0] = pk2(fr0[k], fr0[k]);
            fa[1] = pk2(fr1[k], fr1[k]);
            fa[2] = pk2(fr2[k], fr2[k]);
            fa[3] = pk2(fr3[k], fr3[k]);
            const float* wr = We1 + k * INNER + 2 * jcg;
            #pragma unroll
            for (int p = 0; p < 5; p++) {
                unsigned long long wv = __ldg((const unsigned long long*)(wr + 32 * p));
                #pragma unroll
                for (int i = 0; i < 4; i++) ffma2(acc[i][p], fa[i], wv);
            }
        }
        #pragma unroll
        for (int p = 0; p < 5; p++) {
            int j0 = 2 * jcg + 32 * p;
            float b0 = be1[j0], b1 = be1[j0 + 1];
            #pragma unroll
            for (int i = 0; i < 4; i++) {
                float lo, hi; upk2(acc[i][p], lo, hi);
                int e = ecg + 16 * i;
                sm1[e * MS + j0]     = siluf(lo + b0);
                sm1[e * MS + j0 + 1] = siluf(hi + b1);
            }
        }
    }
    __syncthreads();

    // ---- GEMM2: m = silu(m1 @ We2 + be2), [EB][160] x [160][160] ----
    {
        unsigned long long acc[4][5];
        #pragma unroll
        for (int i = 0; i < 4; i++)
            #pragma unroll
            for (int p = 0; p < 5; p++) acc[i][p] = 0ull;
        const float* fr0 = sm1 + (ecg +  0) * MS;
        const float* fr1 = sm1 + (ecg + 16) * MS;
        const float* fr2 = sm1 + (ecg + 32) * MS;
        const float* fr3 = sm1 + (ecg + 48) * MS;
        #pragma unroll 2
        for (int k = 0; k < INNER; k++) {
            unsigned long long fa[4];
            fa[0] = pk2(fr0[k], fr0[k]);
            fa[1] = pk2(fr1[k], fr1[k]);
            fa[2] = pk2(fr2[k], fr2[k]);
            fa[3] = pk2(fr3[k], fr3[k]);
            const float* wr = We2 + k * INNER + 2 * jcg;
            #pragma unroll
            for (int p = 0; p < 5; p++) {
                unsigned long long wv = __ldg((const unsigned long long*)(wr + 32 * p));
                #pragma unroll
                for (int i = 0; i < 4; i++) ffma2(acc[i][p], fa[i], wv);
            }
        }
        #pragma unroll
        for (int p = 0; p < 5; p++) {
            int j0 = 2 * jcg + 32 * p;
            float b0 = be2[j0], b1 = be2[j0 + 1];
            #pragma unroll
            for (int i = 0; i < 4; i++) {
                float lo, hi; upk2(acc[i][p], lo, hi);
                int e = ecg + 16 * i;
                smm[e * MS + j0]     = siluf(lo + b0);
                smm[e * MS + j0 + 1] = siluf(hi + b1);
            }
        }
    }
    __syncthreads();

    // ---- Wv: vals = m @ Wv, [EB][160] x [160][128] ----
    {
        unsigned long long acc[4][4];
        #pragma unroll
        for (int i = 0; i < 4; i++)
            #pragma unroll
            for (int p = 0; p < 4; p++) acc[i][p] = 0ull;
        const float* fr0 = smm + (ecg +  0) * MS;
        const float* fr1 = smm + (ecg + 16) * MS;
        const float* fr2 = smm + (ecg + 32) * MS;
        const float* fr3 = smm + (ecg + 48) * MS;
        #pragma unroll 2
        for (int k = 0; k < INNER; k++) {
            unsigned long long fa[4];
            fa[0] = pk2(fr0[k], fr0[k]);
            fa[1] = pk2(fr1[k], fr1[k]);
            fa[2] = pk2(fr2[k], fr2[k]);
            fa[3] = pk2(fr3[k], fr3[k]);
            const float* wr = Wv + k * 128 + 2 * jcg;
            #pragma unroll
            for (int p = 0; p < 4; p++) {
                unsigned long long wv = __ldg((const unsigned long long*)(wr + 32 * p));
                #pragma unroll
                for (int i = 0; i < 4; i++) ffma2(acc[i][p], fa[i], wv);
            }
        }
        #pragma unroll
        for (int p = 0; p < 4; p++) {
            int j0 = 2 * jcg + 32 * p;
            #pragma unroll
            for (int i = 0; i < 4; i++) {
                float lo, hi; upk2(acc[i][p], lo, hi);
                int ed = eg + ecg + 16 * i;
                if (ed < E) {
                    g_vals[(size_t)ed * 128 + j0]     = lo;
                    g_vals[(size_t)ed * 128 + j0 + 1] = hi;
                }
            }
        }
    }

    // ---- Wa: logits = m @ Wa, [EB][160] x [160][8] ----
    #pragma unroll
    for (int pass = 0; pass < 2; pass++) {
        int e = (tid >> 3) + 32 * pass;
        int hh = tid & 7;
        const float* mr = smm + e * MS;
        float accl = 0.f;
        #pragma unroll 4
        for (int k = 0; k < INNER; k++) accl += mr[k] * __ldg(Wa + k * 8 + hh);
        int ed = eg + e;
        if (ed < E) g_logits[(size_t)ed * 8 + hh] = accl;
    }

    // ---- Wc: coordinate messages ----
    if (tid < EB) {
        int e = tid;
        const float* mr = smm + e * MS;
        float c = 0.f;
        #pragma unroll 4
        for (int k = 0; k < INNER; k++) c += mr[k] * __ldg(Wc + k);
        float rad = sf[e * FS + 256];
        float s = c / (sqrtf(rad + 1e-5f) + 1.0f);
        int ed = eg + e;
        if (ed < E) {
            g_msgx[(size_t)ed * 3 + 0] = sdiff[e * 3 + 0] * s;
            g_msgx[(size_t)ed * 3 + 1] = sdiff[e * 3 + 1] * s;
            g_msgx[(size_t)ed * 3 + 2] = sdiff[e * 3 + 2] * s;
        }
    }
}

// ---------------- node-centric aggregation (softmax + weighted sum + coords) ----------------
__global__ void __launch_bounds__(128) k_agg(const float* __restrict__ coords,
                                             float* __restrict__ out_coords)
{
    const int n = blockIdx.x, tid = threadIdx.x;
    const int s0 = g_start[n];
    const int deg = g_start[n + 1] - s0;
    __shared__ int sh_e[16];
    __shared__ float sh_w[16][8];
    __shared__ float red[16][8];
    __shared__ float sh_mx[8], sh_den[8];
    const int slot = tid >> 3, hh = tid & 7;

    // pass 1: per-head max
    float mloc = -3.0e38f;
    for (int c = 0; c < deg; c += 16) {
        int len = min(16, deg - c);
        if (tid < len) sh_e[tid] = g_eid[s0 + c + tid];
        __syncthreads();
        if (slot < len) mloc = fmaxf(mloc, g_logits[(size_t)sh_e[slot] * 8 + hh]);
        __syncthreads();
    }
    red[slot][hh] = mloc;
    __syncthreads();
    for (int o = 8; o > 0; o >>= 1) {
        if (slot < o) red[slot][hh] = fmaxf(red[slot][hh], red[slot + o][hh]);
        __syncthreads();
    }
    if (slot == 0) sh_mx[hh] = red[0][hh];
    __syncthreads();

    // pass 2: denominator
    float dloc = 0.f;
    for (int c = 0; c < deg; c += 16) {
        int len = min(16, deg - c);
        if (tid < len) sh_e[tid] = g_eid[s0 + c + tid];
        __syncthreads();
        if (slot < len) dloc += __expf(g_logits[(size_t)sh_e[slot] * 8 + hh] - sh_mx[hh]);
        __syncthreads();
    }
    red[slot][hh] = dloc;
    __syncthreads();
    for (int o = 8; o > 0; o >>= 1) {
        if (slot < o) red[slot][hh] += red[slot + o][hh];
        __syncthreads();
    }
    if (slot == 0) sh_den[hh] = red[0][hh];
    __syncthreads();

    // pass 3: weighted aggregation + coord scatter
    float acc = 0.f;
    float cacc = 0.f;
    for (int c = 0; c < deg; c += 16) {
        int len = min(16, deg - c);
        if (tid < len) sh_e[tid] = g_eid[s0 + c + tid];
        __syncthreads();
        if (slot < len)
            sh_w[slot][hh] = __expf(g_logits[(size_t)sh_e[slot] * 8 + hh] - sh_mx[hh]) / sh_den[hh];
        __syncthreads();
        for (int i = 0; i < len; i++) {
            int e = sh_e[i];
            acc += g_vals[(size_t)e * 128 + tid] * sh_w[i][tid >> 4];
            if (tid < 3) cacc += g_msgx[(size_t)e * 3 + tid];
        }
        __syncthreads();
    }
    g_hagg[(size_t)n * 128 + tid] = acc;
    if (tid < 3) out_coords[n * 3 + tid] = coords[n * 3 + tid] + cacc;
}

// ---------------- fused node kernel ----------------
__global__ void __launch_bounds__(128) k_node(
    const float* __restrict__ h, const float* __restrict__ res, const float* __restrict__ y,
    const float* __restrict__ Wo,
    const float* __restrict__ Wn1, const float* __restrict__ bn1,
    const float* __restrict__ Wn2, const float* __restrict__ bn2,
    const float* __restrict__ Wf1, const float* __restrict__ bf1,
    const float* __restrict__ Wf2, const float* __restrict__ bf2,
    float* __restrict__ out_h2, float* __restrict__ out_res2)
{
    const int n = blockIdx.x, d = threadIdx.x;
    __shared__ float sv[160];
    __shared__ float st[160];
    __shared__ float sy[64];
    __shared__ float rs[8];

    sv[d] = g_hagg[(size_t)n * 128 + d];
    if (d < 64) sy[d] = y[(size_t)n * 64 + d];
    __syncthreads();

    // f2 = h_agg @ Wo
    float f2 = 0.f;
    #pragma unroll 4
    for (int k = 0; k < 128; k++) f2 += sv[k] * __ldg(Wo + k * 128 + d);
    float resv = res[(size_t)n * 128 + d];
    float x = h[(size_t)n * 128 + d] + f2;

    // ada_ln #1
    float s = x, q = x * x;
    #pragma unroll
    for (int o = 16; o; o >>= 1) { s += __shfl_xor_sync(~0u, s, o); q += __shfl_xor_sync(~0u, q, o); }
    __syncthreads();
    if ((d & 31) == 0) { rs[d >> 5] = s; rs[4 + (d >> 5)] = q; }
    __syncthreads();
    s = rs[0] + rs[1] + rs[2] + rs[3];
    q = rs[4] + rs[5] + rs[6] + rs[7];
    float mu = s * (1.f / 128.f);
    float var = q * (1.f / 128.f) - mu * mu;
    float xn = (x - mu) * rsqrtf(var + 1e-5f);
    float sc = bf1[d], sf_ = bf1[128 + d];
    #pragma unroll 4
    for (int k = 0; k < 64; k++) {
        float yv = sy[k];
        sc  += yv * __ldg(Wf1 + k * 256 + d);
        sf_ += yv * __ldg(Wf1 + k * 256 + 128 + d);
    }
    float h1 = xn * (1.f + sc) + sf_;
    __syncthreads();
    sv[d] = h1;
    __syncthreads();

    // node MLP: t = silu(h1 @ Wn1 + bn1) (160 outputs)
    float ta = bn1[d];
    #pragma unroll 4
    for (int k = 0; k < 128; k++) ta += sv[k] * __ldg(Wn1 + k * 160 + d);
    ta = siluf(ta);
    float tb = 0.f;
    if (d < 32) {
        tb = bn1[128 + d];
        #pragma unroll 4
        for (int k = 0; k < 128; k++) tb += sv[k] * __ldg(Wn1 + k * 160 + 128 + d);
        tb = siluf(tb);
    }
    st[d] = ta;
    if (d < 32) st[128 + d] = tb;
    __syncthreads();

    float f3 = bn2[d];
    #pragma unroll 4
    for (int k = 0; k < 160; k++) f3 += st[k] * __ldg(Wn2 + k * 128 + d);

    out_res2[(size_t)n * 128 + d] = resv + f2 + f3;

    // ada_ln #2
    float x2 = h1 + f3;
    s = x2; q = x2 * x2;
    #pragma unroll
    for (int o = 16; o; o >>= 1) { s += __shfl_xor_sync(~0u, s, o); q += __shfl_xor_sync(~0u, q, o); }
    __syncthreads();
    if ((d & 31) == 0) { rs[d >> 5] = s; rs[4 + (d >> 5)] = q; }
    __syncthreads();
    s = rs[0] + rs[1] + rs[2] + rs[3];
    q = rs[4] + rs[5] + rs[6] + rs[7];
    mu = s * (1.f / 128.f);
    var = q * (1.f / 128.f) - mu * mu;
    xn = (x2 - mu) * rsqrtf(var + 1e-5f);
    sc = bf2[d]; sf_ = bf2[128 + d];
    #pragma unroll 4
    for (int k = 0; k < 64; k++) {
        float yv = sy[k];
        sc  += yv * __ldg(Wf2 + k * 256 + d);
        sf_ += yv * __ldg(Wf2 + k * 256 + 128 + d);
    }
    out_h2[(size_t)n * 128 + d] = xn * (1.f + sc) + sf_;
}

// ---------------- launch ----------------
extern "C" void kernel_launch(void* const* d_in, const int* in_sizes, int n_in,
                              void* d_out, int out_size) {
    const float* h      = (const float*)d_in[0];
    const float* coords = (const float*)d_in[1];
    const float* a      = (const float*)d_in[2];
    const float* y      = (const float*)d_in[3];
    const float* res    = (const float*)d_in[4];
    const int*   src    = (const int*)d_in[5];
    const int*   dst    = (const int*)d_in[6];
    const float* We1 = (const float*)d_in[7];
    const float* be1 = (const float*)d_in[8];
    const float* We2 = (const float*)d_in[9];
    const float* be2 = (const float*)d_in[10];
    const float* Wc  = (const float*)d_in[11];
    const float* Wv  = (const float*)d_in[12];
    const float* Wa  = (const float*)d_in[13];
    const float* Wo  = (const float*)d_in[14];
    const float* Wn1 = (const float*)d_in[15];
    const float* bn1 = (const float*)d_in[16];
    const float* Wn2 = (const float*)d_in[17];
    const float* bn2 = (const float*)d_in[18];
    const float* Wf1 = (const float*)d_in[19];
    const float* bf1 = (const float*)d_in[20];
    const float* Wf2 = (const float*)d_in[21];
    const float* bf2 = (const float*)d_in[22];

    const int N = in_sizes[0] / HID;
    const int E = in_sizes[5];

    float* out = (float*)d_out;
    float* out_h2 = out;
    float* out_coords = out + (size_t)N * HID;
    float* out_res2 = out + (size_t)N * HID + (size_t)N * 3;

    const int SMEM = (EB * FS + 2 * EB * MS + EB * 3) * (int)sizeof(float);
    cudaFuncSetAttribute(k_edge, cudaFuncAttributeMaxDynamicSharedMemorySize, SMEM);

    k_zero<<<(N + 255) / 256, 256>>>(N);
    k_deg<<<(E + 255) / 256, 256>>>(dst, E);
    k_scan<<<1, 1024>>>(N);
    k_fill<<<(E + 255) / 256, 256>>>(dst, E);
    k_edge<<<(E + EB - 1) / EB, 256, SMEM>>>(h, coords, a, src, dst,
                                             We1, be1, We2, be2, Wc, Wv, Wa, E);
    k_agg<<<N, 128>>>(coords, out_coords);
    k_node<<<N, 128>>>(h, res, y, Wo, Wn1, bn1, Wn2, bn2, Wf1, bf1, Wf2, bf2,
                       out_h2, out_res2);
}

// round 3
// speedup vs baseline: 1.2646x; 1.2646x over previous
#include <cuda_runtime.h>
#include <math.h>

#define NMAX 25000
#define EMAX 400000
#define HID 128
#define INNER 160
#define MSGF 273
#define FS 276     // f shared row stride (floats, mult of 4)
#define MS 164     // m/m1 shared row stride (floats, mult of 4)
#define EB 64      // edges per block
#define NB 32      // nodes per block (k_node)

// ---------------- scratch ----------------
__device__ float g_vals[(size_t)EMAX * 128];
__device__ float g_logits[(size_t)EMAX * 8];
__device__ float g_msgx[(size_t)EMAX * 3];
__device__ float g_hagg[(size_t)NMAX * 128];
__device__ int g_deg[NMAX];
__device__ int g_cursor[NMAX];
__device__ int g_start[NMAX + 1];
__device__ int g_eid[EMAX];

// ---------------- helpers ----------------
typedef unsigned long long ull;
__device__ __forceinline__ ull pk2(float a, float b) {
    ull r;
    asm("mov.b64 %0, {%1, %2};" : "=l"(r) : "r"(__float_as_uint(a)), "r"(__float_as_uint(b)));
    return r;
}
__device__ __forceinline__ void upk2(ull v, float &a, float &b) {
    unsigned int lo, hi;
    asm("mov.b64 {%0, %1}, %2;" : "=r"(lo), "=r"(hi) : "l"(v));
    a = __uint_as_float(lo); b = __uint_as_float(hi);
}
__device__ __forceinline__ void ffma2(ull &d, ull a, ull b) {
    asm("fma.rn.f32x2 %0, %1, %2, %3;" : "=l"(d) : "l"(a), "l"(b), "l"(d));
}
__device__ __forceinline__ float siluf(float x) { return x / (1.0f + __expf(-x)); }
__device__ __forceinline__ float getc(const float4& v, int kk) {
    return kk == 0 ? v.x : kk == 1 ? v.y : kk == 2 ? v.z : v.w;
}

// ---------------- CSR build ----------------
__global__ void k_zero(int n) {
    int i = blockIdx.x * blockDim.x + threadIdx.x;
    if (i < n) { g_deg[i] = 0; g_cursor[i] = 0; }
}
__global__ void k_deg(const int* __restrict__ dst, int E) {
    int e = blockIdx.x * blockDim.x + threadIdx.x;
    if (e < E) atomicAdd(&g_deg[dst[e]], 1);
}
__global__ void k_scan(int n) {
    __shared__ int sh[1024];
    int carry = 0;
    for (int base = 0; base < n; base += 1024) {
        int i = base + threadIdx.x;
        int x = (i < n) ? g_deg[i] : 0;
        sh[threadIdx.x] = x;
        __syncthreads();
        for (int off = 1; off < 1024; off <<= 1) {
            int v = (threadIdx.x >= off) ? sh[threadIdx.x - off] : 0;
            __syncthreads();
            sh[threadIdx.x] += v;
            __syncthreads();
        }
        if (i < n) g_start[i] = carry + sh[threadIdx.x] - x;
        carry += sh[1023];
        __syncthreads();
    }
    if (threadIdx.x == 0) g_start[n] = carry;
}
__global__ void k_fill(const int* __restrict__ dst, int E) {
    int e = blockIdx.x * blockDim.x + threadIdx.x;
    if (e < E) {
        int d = dst[e];
        int p = atomicAdd(&g_cursor[d], 1);
        g_eid[g_start[d] + p] = e;
    }
}

// ---------------- fused edge kernel ----------------
__global__ void __launch_bounds__(256, 2) k_edge(
    const float* __restrict__ h, const float* __restrict__ coords, const float* __restrict__ a,
    const int* __restrict__ src, const int* __restrict__ dst,
    const float* __restrict__ We1, const float* __restrict__ be1,
    const float* __restrict__ We2, const float* __restrict__ be2,
    const float* __restrict__ Wc, const float* __restrict__ Wv, const float* __restrict__ Wa,
    int E)
{
    extern __shared__ float sm_e[];
    float* sf    = sm_e;              // [EB][FS]
    float* sm1   = sf + EB * FS;      // [EB][MS]
    float* sdiff = sm1 + EB * MS;     // [EB][3]
    float* srad  = sdiff + EB * 3;    // [EB]
    float* smm   = sf;                // alias: GEMM2 output overwrites gathered f

    const int tid = threadIdx.x;
    const int eg = blockIdx.x * EB;
    const int warp = tid >> 5, lane = tid & 31;

    // ---- gather f = [h_src(128), h_dst(128), r^2(1), a(16)] ----
    for (int e = warp; e < EB; e += 8) {
        int ed = eg + e; if (ed > E - 1) ed = E - 1;
        int si = src[ed], di = dst[ed];
        float4 hv = ((const float4*)(h + (size_t)si * 128))[lane];
        *(float4*)(sf + e * FS + 4 * lane) = hv;
        float4 hd = ((const float4*)(h + (size_t)di * 128))[lane];
        *(float4*)(sf + e * FS + 128 + 4 * lane) = hd;
        if (lane < 4) {
            float4 av = ((const float4*)(a + (size_t)ed * 16))[lane];
            int c = e * FS + 257 + 4 * lane;
            sf[c] = av.x; sf[c + 1] = av.y; sf[c + 2] = av.z; sf[c + 3] = av.w;
        }
        if (lane == 0) {
            float dx = coords[si * 3 + 0] - coords[di * 3 + 0];
            float dy = coords[si * 3 + 1] - coords[di * 3 + 1];
            float dz = coords[si * 3 + 2] - coords[di * 3 + 2];
            float rad = dx * dx + dy * dy + dz * dz;
            sf[e * FS + 256] = rad; srad[e] = rad;
            sdiff[e * 3 + 0] = dx; sdiff[e * 3 + 1] = dy; sdiff[e * 3 + 2] = dz;
        }
    }
    __syncthreads();

    const int ecg = tid >> 4;     // 0..15, rows ecg + 16*i
    const int jcg = tid & 15;     // 0..15, cols 4*jcg + 64*p, + half-panel 128+2*jcg

    // ---- GEMM1: m1 = silu(f @ We1 + be1) [EB][273] x [273][160] ----
    {
        ull acc[4][5];
        #pragma unroll
        for (int i = 0; i < 4; i++) { acc[i][0]=0; acc[i][1]=0; acc[i][2]=0; acc[i][3]=0; acc[i][4]=0; }
        const float* f0 = sf + (ecg +  0) * FS;
        const float* f1 = sf + (ecg + 16) * FS;
        const float* f2p = sf + (ecg + 32) * FS;
        const float* f3p = sf + (ecg + 48) * FS;
        for (int k4 = 0; k4 < 272; k4 += 4) {
            float4 a0 = *(const float4*)(f0 + k4);
            float4 a1 = *(const float4*)(f1 + k4);
            float4 a2 = *(const float4*)(f2p + k4);
            float4 a3 = *(const float4*)(f3p + k4);
            #pragma unroll
            for (int kk = 0; kk < 4; kk++) {
                ull fa[4];
                fa[0] = pk2(getc(a0,kk), getc(a0,kk));
                fa[1] = pk2(getc(a1,kk), getc(a1,kk));
                fa[2] = pk2(getc(a2,kk), getc(a2,kk));
                fa[3] = pk2(getc(a3,kk), getc(a3,kk));
                const float* wr = We1 + (k4 + kk) * INNER;
                float4 w0 = __ldg((const float4*)(wr + 4 * jcg));
                float4 w1 = __ldg((const float4*)(wr + 64 + 4 * jcg));
                float2 w2 = __ldg((const float2*)(wr + 128 + 2 * jcg));
                ull W00 = pk2(w0.x, w0.y), W01 = pk2(w0.z, w0.w);
                ull W10 = pk2(w1.x, w1.y), W11 = pk2(w1.z, w1.w);
                ull W2  = pk2(w2.x, w2.y);
                #pragma unroll
                for (int i = 0; i < 4; i++) {
                    ffma2(acc[i][0], fa[i], W00); ffma2(acc[i][1], fa[i], W01);
                    ffma2(acc[i][2], fa[i], W10); ffma2(acc[i][3], fa[i], W11);
                    ffma2(acc[i][4], fa[i], W2);
                }
            }
        }
        { // tail k = 272
            ull fa[4];
            fa[0] = pk2(f0[272], f0[272]); fa[1] = pk2(f1[272], f1[272]);
            fa[2] = pk2(f2p[272], f2p[272]); fa[3] = pk2(f3p[272], f3p[272]);
            const float* wr = We1 + 272 * INNER;
            float4 w0 = __ldg((const float4*)(wr + 4 * jcg));
            float4 w1 = __ldg((const float4*)(wr + 64 + 4 * jcg));
            float2 w2 = __ldg((const float2*)(wr + 128 + 2 * jcg));
            ull W00 = pk2(w0.x, w0.y), W01 = pk2(w0.z, w0.w);
            ull W10 = pk2(w1.x, w1.y), W11 = pk2(w1.z, w1.w);
            ull W2  = pk2(w2.x, w2.y);
            #pragma unroll
            for (int i = 0; i < 4; i++) {
                ffma2(acc[i][0], fa[i], W00); ffma2(acc[i][1], fa[i], W01);
                ffma2(acc[i][2], fa[i], W10); ffma2(acc[i][3], fa[i], W11);
                ffma2(acc[i][4], fa[i], W2);
            }
        }
        #pragma unroll
        for (int i = 0; i < 4; i++) {
            float* orow = sm1 + (ecg + 16 * i) * MS;
            float lo, hi;
            int c = 4 * jcg;
            upk2(acc[i][0], lo, hi);
            orow[c]   = siluf(lo + __ldg(be1 + c));   orow[c+1] = siluf(hi + __ldg(be1 + c + 1));
            upk2(acc[i][1], lo, hi);
            orow[c+2] = siluf(lo + __ldg(be1 + c + 2)); orow[c+3] = siluf(hi + __ldg(be1 + c + 3));
            c = 64 + 4 * jcg;
            upk2(acc[i][2], lo, hi);
            orow[c]   = siluf(lo + __ldg(be1 + c));   orow[c+1] = siluf(hi + __ldg(be1 + c + 1));
            upk2(acc[i][3], lo, hi);
            orow[c+2] = siluf(lo + __ldg(be1 + c + 2)); orow[c+3] = siluf(hi + __ldg(be1 + c + 3));
            c = 128 + 2 * jcg;
            upk2(acc[i][4], lo, hi);
            orow[c]   = siluf(lo + __ldg(be1 + c));   orow[c+1] = siluf(hi + __ldg(be1 + c + 1));
        }
    }
    __syncthreads();

    // ---- GEMM2: m = silu(m1 @ We2 + be2) [EB][160] x [160][160] (out aliases sf) ----
    {
        ull acc[4][5];
        #pragma unroll
        for (int i = 0; i < 4; i++) { acc[i][0]=0; acc[i][1]=0; acc[i][2]=0; acc[i][3]=0; acc[i][4]=0; }
        const float* f0 = sm1 + (ecg +  0) * MS;
        const float* f1 = sm1 + (ecg + 16) * MS;
        const float* f2p = sm1 + (ecg + 32) * MS;
        const float* f3p = sm1 + (ecg + 48) * MS;
        for (int k4 = 0; k4 < INNER; k4 += 4) {
            float4 a0 = *(const float4*)(f0 + k4);
            float4 a1 = *(const float4*)(f1 + k4);
            float4 a2 = *(const float4*)(f2p + k4);
            float4 a3 = *(const float4*)(f3p + k4);
            #pragma unroll
            for (int kk = 0; kk < 4; kk++) {
                ull fa[4];
                fa[0] = pk2(getc(a0,kk), getc(a0,kk));
                fa[1] = pk2(getc(a1,kk), getc(a1,kk));
                fa[2] = pk2(getc(a2,kk), getc(a2,kk));
                fa[3] = pk2(getc(a3,kk), getc(a3,kk));
                const float* wr = We2 + (k4 + kk) * INNER;
                float4 w0 = __ldg((const float4*)(wr + 4 * jcg));
                float4 w1 = __ldg((const float4*)(wr + 64 + 4 * jcg));
                float2 w2 = __ldg((const float2*)(wr + 128 + 2 * jcg));
                ull W00 = pk2(w0.x, w0.y), W01 = pk2(w0.z, w0.w);
                ull W10 = pk2(w1.x, w1.y), W11 = pk2(w1.z, w1.w);
                ull W2  = pk2(w2.x, w2.y);
                #pragma unroll
                for (int i = 0; i < 4; i++) {
                    ffma2(acc[i][0], fa[i], W00); ffma2(acc[i][1], fa[i], W01);
                    ffma2(acc[i][2], fa[i], W10); ffma2(acc[i][3], fa[i], W11);
                    ffma2(acc[i][4], fa[i], W2);
                }
            }
        }
        __syncthreads();   // everyone done reading sm1 before... (actually writes go to smm=sf; sm1 untouched) — sync for sf overwrite vs nothing reading sf: GEMM1 done long ago. Keep for safety of smm stores vs any residual sf reads.
        #pragma unroll
        for (int i = 0; i < 4; i++) {
            float* orow = smm + (ecg + 16 * i) * MS;
            float lo, hi;
            int c = 4 * jcg;
            upk2(acc[i][0], lo, hi);
            orow[c]   = siluf(lo + __ldg(be2 + c));   orow[c+1] = siluf(hi + __ldg(be2 + c + 1));
            upk2(acc[i][1], lo, hi);
            orow[c+2] = siluf(lo + __ldg(be2 + c + 2)); orow[c+3] = siluf(hi + __ldg(be2 + c + 3));
            c = 64 + 4 * jcg;
            upk2(acc[i][2], lo, hi);
            orow[c]   = siluf(lo + __ldg(be2 + c));   orow[c+1] = siluf(hi + __ldg(be2 + c + 1));
            upk2(acc[i][3], lo, hi);
            orow[c+2] = siluf(lo + __ldg(be2 + c + 2)); orow[c+3] = siluf(hi + __ldg(be2 + c + 3));
            c = 128 + 2 * jcg;
            upk2(acc[i][4], lo, hi);
            orow[c]   = siluf(lo + __ldg(be2 + c));   orow[c+1] = siluf(hi + __ldg(be2 + c + 1));
        }
    }
    __syncthreads();

    // ---- phase 3: vals = m @ Wv (128), logits = m @ Wa (8), coord msg = m @ Wc ----
    {
        ull acc[4][4], accx[4];
        #pragma unroll
        for (int i = 0; i < 4; i++) { acc[i][0]=0; acc[i][1]=0; acc[i][2]=0; acc[i][3]=0; accx[i]=0; }
        const float* f0 = smm + (ecg +  0) * MS;
        const float* f1 = smm + (ecg + 16) * MS;
        const float* f2p = smm + (ecg + 32) * MS;
        const float* f3p = smm + (ecg + 48) * MS;
        for (int k4 = 0; k4 < INNER; k4 += 4) {
            float4 a0 = *(const float4*)(f0 + k4);
            float4 a1 = *(const float4*)(f1 + k4);
            float4 a2 = *(const float4*)(f2p + k4);
            float4 a3 = *(const float4*)(f3p + k4);
            #pragma unroll
            for (int kk = 0; kk < 4; kk++) {
                int k = k4 + kk;
                ull fa[4];
                fa[0] = pk2(getc(a0,kk), getc(a0,kk));
                fa[1] = pk2(getc(a1,kk), getc(a1,kk));
                fa[2] = pk2(getc(a2,kk), getc(a2,kk));
                fa[3] = pk2(getc(a3,kk), getc(a3,kk));
                float4 w0 = __ldg((const float4*)(Wv + k * 128 + 4 * jcg));
                float4 w1 = __ldg((const float4*)(Wv + k * 128 + 64 + 4 * jcg));
                ull W00 = pk2(w0.x, w0.y), W01 = pk2(w0.z, w0.w);
                ull W10 = pk2(w1.x, w1.y), W11 = pk2(w1.z, w1.w);
                ull WX = 0;
                if (jcg < 4) {
                    float2 wa = __ldg((const float2*)(Wa + k * 8 + 2 * jcg));
                    WX = pk2(wa.x, wa.y);
                } else if (jcg == 8) {
                    WX = pk2(__ldg(Wc + k), 0.0f);
                }
                #pragma unroll
                for (int i = 0; i < 4; i++) {
                    ffma2(acc[i][0], fa[i], W00); ffma2(acc[i][1], fa[i], W01);
                    ffma2(acc[i][2], fa[i], W10); ffma2(acc[i][3], fa[i], W11);
                    ffma2(accx[i], fa[i], WX);
                }
            }
        }
        #pragma unroll
        for (int i = 0; i < 4; i++) {
            int e = ecg + 16 * i;
            int ed = eg + e;
            if (ed < E) {
                float x0, x1, x2v, x3v;
                upk2(acc[i][0], x0, x1); upk2(acc[i][1], x2v, x3v);
                *(float4*)(g_vals + (size_t)ed * 128 + 4 * jcg) = make_float4(x0, x1, x2v, x3v);
                upk2(acc[i][2], x0, x1); upk2(acc[i][3], x2v, x3v);
                *(float4*)(g_vals + (size_t)ed * 128 + 64 + 4 * jcg) = make_float4(x0, x1, x2v, x3v);
                if (jcg < 4) {
                    float l0, l1; upk2(accx[i], l0, l1);
                    *(float2*)(g_logits + (size_t)ed * 8 + 2 * jcg) = make_float2(l0, l1);
                }
                if (jcg == 8) {
                    float cc, du; upk2(accx[i], cc, du);
                    float s = cc / (sqrtf(srad[e] + 1e-5f) + 1.0f);
                    g_msgx[(size_t)ed * 3 + 0] = sdiff[e * 3 + 0] * s;
                    g_msgx[(size_t)ed * 3 + 1] = sdiff[e * 3 + 1] * s;
                    g_msgx[(size_t)ed * 3 + 2] = sdiff[e * 3 + 2] * s;
                }
            }
        }
    }
}

// ---------------- node-centric aggregation ----------------
__global__ void __launch_bounds__(128) k_agg(const float* __restrict__ coords,
                                             float* __restrict__ out_coords)
{
    const int n = blockIdx.x, tid = threadIdx.x;
    const int s0 = g_start[n];
    const int deg = g_start[n + 1] - s0;
    __shared__ int sh_e[16];
    __shared__ float sh_w[16][8];
    __shared__ float red[16][8];
    __shared__ float sh_mx[8], sh_den[8];
    __shared__ float4 sredv[128];
    const int slot = tid >> 3, hh = tid & 7;

    // pass 1: per-head max
    float mloc = -3.0e38f;
    for (int c = 0; c < deg; c += 16) {
        int len = min(16, deg - c);
        if (tid < len) sh_e[tid] = g_eid[s0 + c + tid];
        __syncthreads();
        if (slot < len) mloc = fmaxf(mloc, g_logits[(size_t)sh_e[slot] * 8 + hh]);
        __syncthreads();
    }
    red[slot][hh] = mloc;
    __syncthreads();
    for (int o = 8; o > 0; o >>= 1) {
        if (slot < o) red[slot][hh] = fmaxf(red[slot][hh], red[slot + o][hh]);
        __syncthreads();
    }
    if (slot == 0) sh_mx[hh] = red[0][hh];
    __syncthreads();

    // pass 2: denominator
    float dloc = 0.f;
    for (int c = 0; c < deg; c += 16) {
        int len = min(16, deg - c);
        if (tid < len) sh_e[tid] = g_eid[s0 + c + tid];
        __syncthreads();
        if (slot < len) dloc += __expf(g_logits[(size_t)sh_e[slot] * 8 + hh] - sh_mx[hh]);
        __syncthreads();
    }
    red[slot][hh] = dloc;
    __syncthreads();
    for (int o = 8; o > 0; o >>= 1) {
        if (slot < o) red[slot][hh] += red[slot + o][hh];
        __syncthreads();
    }
    if (slot == 0) sh_den[hh] = red[0][hh];
    __syncthreads();

    // pass 3: weighted value aggregation (4 edge slots x 32 dim groups)
    const int es = tid >> 5, dg = tid & 31;
    float4 acc = make_float4(0.f, 0.f, 0.f, 0.f);
    for (int c = 0; c < deg; c += 16) {
        int len = min(16, deg - c);
        if (tid < len) sh_e[tid] = g_eid[s0 + c + tid];
        __syncthreads();
        if (slot < len)
            sh_w[slot][hh] = __expf(g_logits[(size_t)sh_e[slot] * 8 + hh] - sh_mx[hh]) / sh_den[hh];
        __syncthreads();
        for (int i = es; i < len; i += 4) {
            int e = sh_e[i];
            float4 v = *(const float4*)(g_vals + (size_t)e * 128 + 4 * dg);
            float w = sh_w[i][dg >> 2];
            acc.x += v.x * w; acc.y += v.y * w; acc.z += v.z * w; acc.w += v.w * w;
        }
        __syncthreads();
    }
    sredv[tid] = acc;
    __syncthreads();
    if (es == 0) {
        float4 b = sredv[tid + 32], cc = sredv[tid + 64], d = sredv[tid + 96];
        acc.x += b.x + cc.x + d.x; acc.y += b.y + cc.y + d.y;
        acc.z += b.z + cc.z + d.z; acc.w += b.w + cc.w + d.w;
        *(float4*)(g_hagg + (size_t)n * 128 + 4 * dg) = acc;
    }
    if (tid < 3) {
        float cacc = 0.f;
        for (int i = 0; i < deg; i++) cacc += g_msgx[(size_t)g_eid[s0 + i] * 3 + tid];
        out_coords[n * 3 + tid] = coords[n * 3 + tid] + cacc;
    }
}

// ---------------- batched node GEMM helpers ----------------
template<int K, int NP, int C>
__device__ __forceinline__ void gemm_n(const float* __restrict__ sIn, int is,
                                       const float* __restrict__ W,
                                       ull (&acc)[4][NP][2]) {
    const int tid = threadIdx.x;
    const int ecg = tid >> 5, jcg = tid & 31;
    #pragma unroll
    for (int i = 0; i < 4; i++)
        #pragma unroll
        for (int p = 0; p < NP; p++) { acc[i][p][0] = 0; acc[i][p][1] = 0; }
    for (int k4 = 0; k4 < K; k4 += 4) {
        float4 av[4];
        #pragma unroll
        for (int i = 0; i < 4; i++) av[i] = *(const float4*)(sIn + (ecg + 8 * i) * is + k4);
        #pragma unroll
        for (int kk = 0; kk < 4; kk++) {
            ull fa[4];
            #pragma unroll
            for (int i = 0; i < 4; i++) { float c = getc(av[i], kk); fa[i] = pk2(c, c); }
            const float* wr = W + (k4 + kk) * C + 4 * jcg;
            #pragma unroll
            for (int p = 0; p < NP; p++) {
                if ((C % 128 == 0) || (128 * p + 4 * jcg < C)) {
                    float4 wv = __ldg((const float4*)(wr + 128 * p));
                    ull w0 = pk2(wv.x, wv.y), w1 = pk2(wv.z, wv.w);
                    #pragma unroll
                    for (int i = 0; i < 4; i++) { ffma2(acc[i][p][0], fa[i], w0); ffma2(acc[i][p][1], fa[i], w1); }
                }
            }
        }
    }
}

template<int NP, int C>
__device__ __forceinline__ void store_acc(ull (&acc)[4][NP][2], float* sOut, int os,
                                          const float* bias, bool dosilu) {
    const int tid = threadIdx.x, ecg = tid >> 5, jcg = tid & 31;
    #pragma unroll
    for (int i = 0; i < 4; i++) {
        int r = ecg + 8 * i;
        #pragma unroll
        for (int p = 0; p < NP; p++) {
            int c0 = 128 * p + 4 * jcg;
            if ((C % 128 == 0) || (c0 < C)) {
                float v0, v1, v2, v3;
                upk2(acc[i][p][0], v0, v1); upk2(acc[i][p][1], v2, v3);
                if (bias) {
                    v0 += __ldg(bias + c0); v1 += __ldg(bias + c0 + 1);
                    v2 += __ldg(bias + c0 + 2); v3 += __ldg(bias + c0 + 3);
                }
                if (dosilu) { v0 = siluf(v0); v1 = siluf(v1); v2 = siluf(v2); v3 = siluf(v3); }
                *(float4*)(sOut + r * os + c0) = make_float4(v0, v1, v2, v3);
            }
        }
    }
}

__device__ __forceinline__ void film_store(ull (&acc)[4][2][2], float* sScale, float* sShift,
                                           const float* bias) {
    const int tid = threadIdx.x, ecg = tid >> 5, jcg = tid & 31;
    #pragma unroll
    for (int i = 0; i < 4; i++) {
        int r = ecg + 8 * i;
        int c0 = 4 * jcg;
        float v0, v1, v2, v3;
        upk2(acc[i][0][0], v0, v1); upk2(acc[i][0][1], v2, v3);
        v0 += __ldg(bias + c0); v1 += __ldg(bias + c0 + 1);
        v2 += __ldg(bias + c0 + 2); v3 += __ldg(bias + c0 + 3);
        *(float4*)(sScale + r * 132 + c0) = make_float4(v0, v1, v2, v3);
        upk2(acc[i][1][0], v0, v1); upk2(acc[i][1][1], v2, v3);
        v0 += __ldg(bias + 128 + c0); v1 += __ldg(bias + 128 + c0 + 1);
        v2 += __ldg(bias + 128 + c0 + 2); v3 += __ldg(bias + 128 + c0 + 3);
        *(float4*)(sShift + r * 164 + c0) = make_float4(v0, v1, v2, v3);
    }
}

__device__ __forceinline__ void ln_stats(const float* sX, float* sMu, float* sRs) {
    int w = threadIdx.x >> 5, lane = threadIdx.x & 31;
    #pragma unroll
    for (int rr = 0; rr < 4; rr++) {
        int r = w * 4 + rr;
        float4 v = *(const float4*)(sX + r * 132 + 4 * lane);
        float s = v.x + v.y + v.z + v.w;
        float q = v.x * v.x + v.y * v.y + v.z * v.z + v.w * v.w;
        #pragma unroll
        for (int o = 16; o; o >>= 1) {
            s += __shfl_xor_sync(~0u, s, o);
            q += __shfl_xor_sync(~0u, q, o);
        }
        if (lane == 0) {
            float mu = s * (1.f / 128.f);
            float var = q * (1.f / 128.f) - mu * mu;
            sMu[r] = mu; sRs[r] = rsqrtf(var + 1e-5f);
        }
    }
}

// ---------------- batched node kernel (32 nodes/block) ----------------
__global__ void __launch_bounds__(256, 2) k_node(
    const float* __restrict__ h, const float* __restrict__ res, const float* __restrict__ y,
    const float* __restrict__ Wo,
    const float* __restrict__ Wn1, const float* __restrict__ bn1,
    const float* __restrict__ Wn2, const float* __restrict__ bn2,
    const float* __restrict__ Wf1, const float* __restrict__ bf1,
    const float* __restrict__ Wf2, const float* __restrict__ bf2,
    float* __restrict__ out_h2, float* __restrict__ out_res2, int N)
{
    extern __shared__ float sm_n[];
    float* sA  = sm_n;                 // [32][164]
    float* sB  = sA + 32 * 164;        // [32][132]
    float* sC  = sB + 32 * 132;        // [32][132]
    float* sY  = sC + 32 * 132;        // [32][68]
    float* sMu = sY + 32 * 68;         // [32]
    float* sRs = sMu + 32;             // [32]

    const int nb = blockIdx.x * NB;
    const int tid = threadIdx.x;

    // stage h_agg and y
    for (int idx = tid; idx < 32 * 128; idx += 256) {
        int r = idx >> 7, c = idx & 127;
        int n = min(nb + r, N - 1);
        sB[r * 132 + c] = g_hagg[(size_t)n * 128 + c];
    }
    for (int idx = tid; idx < 32 * 64; idx += 256) {
        int r = idx >> 6, c = idx & 63;
        int n = min(nb + r, N - 1);
        sY[r * 68 + c] = y[(size_t)n * 64 + c];
    }
    __syncthreads();

    // f2 = h_agg @ Wo
    {
        ull acc[4][1][2];
        gemm_n<128, 1, 128>(sB, 132, Wo, acc);
        store_acc<1, 128>(acc, sC, 132, nullptr, false);
    }
    __syncthreads();

    // x = h + f2 (keep f2 in regs)
    float f2r[16];
    #pragma unroll
    for (int t = 0; t < 16; t++) {
        int idx = tid + 256 * t;
        int r = idx >> 7, c = idx & 127;
        int n = min(nb + r, N - 1);
        float f2v = sC[r * 132 + c];
        f2r[t] = f2v;
        sB[r * 132 + c] = h[(size_t)n * 128 + c] + f2v;
    }
    __syncthreads();
    ln_stats(sB, sMu, sRs);
    __syncthreads();

    // FiLM1: scale -> sC, shift -> sA
    {
        ull acc[4][2][2];
        gemm_n<64, 2, 256>(sY, 68, Wf1, acc);
        film_store(acc, sC, sA, bf1);
    }
    __syncthreads();

    // h1 = xn*(1+scale)+shift -> sB
    #pragma unroll
    for (int t = 0; t < 16; t++) {
        int idx = tid + 256 * t;
        int r = idx >> 7, c = idx & 127;
        float x = sB[r * 132 + c];
        float xn = (x - sMu[r]) * sRs[r];
        sB[r * 132 + c] = xn * (1.f + sC[r * 132 + c]) + sA[r * 164 + c];
    }
    __syncthreads();

    // t = silu(h1 @ Wn1 + bn1) -> sA
    {
        ull acc[4][2][2];
        gemm_n<128, 2, 160>(sB, 132, Wn1, acc);
        store_acc<2, 160>(acc, sA, 164, bn1, true);
    }
    __syncthreads();

    // f3 = t @ Wn2 + bn2 -> sC
    {
        ull acc[4][1][2];
        gemm_n<160, 1, 128>(sA, 164, Wn2, acc);
        store_acc<1, 128>(acc, sC, 132, bn2, false);
    }
    __syncthreads();

    // res2 = res + f2 + f3; x2 = h1 + f3 -> sB
    #pragma unroll
    for (int t = 0; t < 16; t++) {
        int idx = tid + 256 * t;
        int r = idx >> 7, c = idx & 127;
        float f3 = sC[r * 132 + c];
        int n = nb + r;
        if (n < N) out_res2[(size_t)n * 128 + c] = res[(size_t)n * 128 + c] + f2r[t] + f3;
        sB[r * 132 + c] += f3;
    }
    __syncthreads();
    ln_stats(sB, sMu, sRs);
    __syncthreads();

    // FiLM2
    {
        ull acc[4][2][2];
        gemm_n<64, 2, 256>(sY, 68, Wf2, acc);
        film_store(acc, sC, sA, bf2);
    }
    __syncthreads();

    // h2 out
    #pragma unroll
    for (int t = 0; t < 16; t++) {
        int idx = tid + 256 * t;
        int r = idx >> 7, c = idx & 127;
        int n = nb + r;
        if (n < N) {
            float xn = (sB[r * 132 + c] - sMu[r]) * sRs[r];
            out_h2[(size_t)n * 128 + c] = xn * (1.f + sC[r * 132 + c]) + sA[r * 164 + c];
        }
    }
}

// ---------------- launch ----------------
extern "C" void kernel_launch(void* const* d_in, const int* in_sizes, int n_in,
                              void* d_out, int out_size) {
    const float* h      = (const float*)d_in[0];
    const float* coords = (const float*)d_in[1];
    const float* a      = (const float*)d_in[2];
    const float* y      = (const float*)d_in[3];
    const float* res    = (const float*)d_in[4];
    const int*   src    = (const int*)d_in[5];
    const int*   dst    = (const int*)d_in[6];
    const float* We1 = (const float*)d_in[7];
    const float* be1 = (const float*)d_in[8];
    const float* We2 = (const float*)d_in[9];
    const float* be2 = (const float*)d_in[10];
    const float* Wc  = (const float*)d_in[11];
    const float* Wv  = (const float*)d_in[12];
    const float* Wa  = (const float*)d_in[13];
    const float* Wo  = (const float*)d_in[14];
    const float* Wn1 = (const float*)d_in[15];
    const float* bn1 = (const float*)d_in[16];
    const float* Wn2 = (const float*)d_in[17];
    const float* bn2 = (const float*)d_in[18];
    const float* Wf1 = (const float*)d_in[19];
    const float* bf1 = (const float*)d_in[20];
    const float* Wf2 = (const float*)d_in[21];
    const float* bf2 = (const float*)d_in[22];

    const int N = in_sizes[0] / HID;
    const int E = in_sizes[5];

    float* out = (float*)d_out;
    float* out_h2 = out;
    float* out_coords = out + (size_t)N * HID;
    float* out_res2 = out + (size_t)N * HID + (size_t)N * 3;

    const int SMEM_E = (EB * FS + EB * MS + EB * 3 + EB) * (int)sizeof(float);
    const int SMEM_N = (32 * 164 + 32 * 132 * 2 + 32 * 68 + 64) * (int)sizeof(float);
    cudaFuncSetAttribute(k_edge, cudaFuncAttributeMaxDynamicSharedMemorySize, SMEM_E);
    cudaFuncSetAttribute(k_node, cudaFuncAttributeMaxDynamicSharedMemorySize, SMEM_N);

    k_zero<<<(N + 255) / 256, 256>>>(N);
    k_deg<<<(E + 255) / 256, 256>>>(dst, E);
    k_scan<<<1, 1024>>>(N);
    // k_edge placed 4th so the fixed ncu skip-window captures it
    k_edge<<<(E + EB - 1) / EB, 256, SMEM_E>>>(h, coords, a, src, dst,
                                               We1, be1, We2, be2, Wc, Wv, Wa, E);
    k_fill<<<(E + 255) / 256, 256>>>(dst, E);
    k_agg<<<N, 128>>>(coords, out_coords);
    k_node<<<(N + NB - 1) / NB, 256, SMEM_N>>>(h, res, y, Wo, Wn1, bn1, Wn2, bn2,
                                               Wf1, bf1, Wf2, bf2, out_h2, out_res2, N);
}

// round 4
// speedup vs baseline: 3.1329x; 2.4775x over previous
#include <cuda_runtime.h>
#include <math.h>

#define NMAX 25000
#define EMAX 400000
#define HID 128
#define INNER 160
#define EB 64      // edges per block
#define NB 32      // nodes per block (k_node)

// ---------------- scratch ----------------
__device__ float g_m[(size_t)EMAX * 160];      // per-edge message m
__device__ float g_logits[(size_t)EMAX * 8];
__device__ float g_msgx[(size_t)EMAX * 3];
__device__ float g_hagg[(size_t)NMAX * 128];
__device__ float g_P[(size_t)NMAX * 320];      // precomputed h@We1 (src half | dst half)
__device__ int g_deg[NMAX];
__device__ int g_cursor[NMAX];
__device__ int g_start[NMAX + 1];
__device__ int g_eid[EMAX];

// ---------------- helpers ----------------
typedef unsigned long long ull;
__device__ __forceinline__ ull pk2(float a, float b) {
    ull r;
    asm("mov.b64 %0, {%1, %2};" : "=l"(r) : "r"(__float_as_uint(a)), "r"(__float_as_uint(b)));
    return r;
}
__device__ __forceinline__ void upk2(ull v, float &a, float &b) {
    unsigned int lo, hi;
    asm("mov.b64 {%0, %1}, %2;" : "=r"(lo), "=r"(hi) : "l"(v));
    a = __uint_as_float(lo); b = __uint_as_float(hi);
}
__device__ __forceinline__ void ffma2(ull &d, ull a, ull b) {
    asm("fma.rn.f32x2 %0, %1, %2, %3;" : "=l"(d) : "l"(a), "l"(b), "l"(d));
}
__device__ __forceinline__ float siluf(float x) { return x / (1.0f + __expf(-x)); }
__device__ __forceinline__ float getc(const float4& v, int kk) {
    return kk == 0 ? v.x : kk == 1 ? v.y : kk == 2 ? v.z : v.w;
}

// ---------------- CSR build ----------------
__global__ void k_zero(int n) {
    int i = blockIdx.x * blockDim.x + threadIdx.x;
    if (i < n) { g_deg[i] = 0; g_cursor[i] = 0; }
}
__global__ void k_deg(const int* __restrict__ dst, int E) {
    int e = blockIdx.x * blockDim.x + threadIdx.x;
    if (e < E) atomicAdd(&g_deg[dst[e]], 1);
}
__global__ void k_scan(int n) {
    __shared__ int sh[1024];
    int carry = 0;
    for (int base = 0; base < n; base += 1024) {
        int i = base + threadIdx.x;
        int x = (i < n) ? g_deg[i] : 0;
        sh[threadIdx.x] = x;
        __syncthreads();
        for (int off = 1; off < 1024; off <<= 1) {
            int v = (threadIdx.x >= off) ? sh[threadIdx.x - off] : 0;
            __syncthreads();
            sh[threadIdx.x] += v;
            __syncthreads();
        }
        if (i < n) g_start[i] = carry + sh[threadIdx.x] - x;
        carry += sh[1023];
        __syncthreads();
    }
    if (threadIdx.x == 0) g_start[n] = carry;
}
__global__ void k_fill(const int* __restrict__ dst, int E) {
    int e = blockIdx.x * blockDim.x + threadIdx.x;
    if (e < E) {
        int d = dst[e];
        int p = atomicAdd(&g_cursor[d], 1);
        g_eid[g_start[d] + p] = e;
    }
}

// ---------------- precompute P[n] = [h@We1[0:128] | h@We1[128:256]] ----------------
__global__ void __launch_bounds__(256) k_pre(const float* __restrict__ h,
                                             const float* __restrict__ We1, int N)
{
    __shared__ float sH[32][132];
    const int nb = blockIdx.x * 32;
    const int tid = threadIdx.x;
    for (int idx = tid; idx < 32 * 128; idx += 256) {
        int r = idx >> 7, c = idx & 127;
        int n = min(nb + r, N - 1);
        sH[r][c] = h[(size_t)n * 128 + c];
    }
    __syncthreads();

    const int ecg = tid >> 5, jcg = tid & 31;   // rows ecg+8i, cols 4jcg (+tail 128+2jcg for jcg<16)
    ull accA[4][3], accB[4][3];
    #pragma unroll
    for (int i = 0; i < 4; i++)
        #pragma unroll
        for (int p = 0; p < 3; p++) { accA[i][p] = 0; accB[i][p] = 0; }

    for (int k = 0; k < 128; k++) {
        ull fa[4];
        #pragma unroll
        for (int i = 0; i < 4; i++) { float c = sH[ecg + 8 * i][k]; fa[i] = pk2(c, c); }
        const float* w1 = We1 + (size_t)k * INNER;
        const float* w2 = We1 + (size_t)(128 + k) * INNER;
        float4 wa = __ldg((const float4*)(w1 + 4 * jcg));
        float4 wb = __ldg((const float4*)(w2 + 4 * jcg));
        ull A0 = pk2(wa.x, wa.y), A1 = pk2(wa.z, wa.w);
        ull B0 = pk2(wb.x, wb.y), B1 = pk2(wb.z, wb.w);
        ull A2 = 0, B2 = 0;
        if (jcg < 16) {
            float2 ta = __ldg((const float2*)(w1 + 128 + 2 * jcg));
            float2 tb = __ldg((const float2*)(w2 + 128 + 2 * jcg));
            A2 = pk2(ta.x, ta.y); B2 = pk2(tb.x, tb.y);
        }
        #pragma unroll
        for (int i = 0; i < 4; i++) {
            ffma2(accA[i][0], fa[i], A0); ffma2(accA[i][1], fa[i], A1);
            ffma2(accB[i][0], fa[i], B0); ffma2(accB[i][1], fa[i], B1);
            if (jcg < 16) { ffma2(accA[i][2], fa[i], A2); ffma2(accB[i][2], fa[i], B2); }
        }
    }
    #pragma unroll
    for (int i = 0; i < 4; i++) {
        int n = nb + ecg + 8 * i;
        if (n < N) {
            float* out = g_P + (size_t)n * 320;
            float x0, x1, x2, x3;
            upk2(accA[i][0], x0, x1); upk2(accA[i][1], x2, x3);
            *(float4*)(out + 4 * jcg) = make_float4(x0, x1, x2, x3);
            upk2(accB[i][0], x0, x1); upk2(accB[i][1], x2, x3);
            *(float4*)(out + 160 + 4 * jcg) = make_float4(x0, x1, x2, x3);
            if (jcg < 16) {
                upk2(accA[i][2], x0, x1);
                *(float2*)(out + 128 + 2 * jcg) = make_float2(x0, x1);
                upk2(accB[i][2], x0, x1);
                *(float2*)(out + 288 + 2 * jcg) = make_float2(x0, x1);
            }
        }
    }
}

// ---------------- fused edge kernel ----------------
__global__ void __launch_bounds__(256, 3) k_edge(
    const float* __restrict__ coords, const float* __restrict__ a,
    const int* __restrict__ src, const int* __restrict__ dst,
    const float* __restrict__ We1, const float* __restrict__ be1,
    const float* __restrict__ We2, const float* __restrict__ be2,
    const float* __restrict__ Wc, const float* __restrict__ Wa,
    int E)
{
    extern __shared__ float sm_e[];
    float* sm1  = sm_e;               // [64][164]
    float* sA   = sm1 + 64 * 164;     // [64][16]
    float* sRad = sA + 64 * 16;       // [64]
    float* sDx  = sRad + 64;          // [64]
    float* sDy  = sDx + 64;
    float* sDz  = sDy + 64;
    int*   sSrc = (int*)(sDz + 64);   // [64]
    int*   sDst = sSrc + 64;          // [64]

    const int tid = threadIdx.x;
    const int eg = blockIdx.x * EB;
    const int warp = tid >> 5, lane = tid & 31;

    // ---- gather edge extras ----
    for (int e = warp; e < EB; e += 8) {
        int ed = eg + e; if (ed > E - 1) ed = E - 1;
        if (lane < 16) sA[e * 16 + lane] = __ldg(a + (size_t)ed * 16 + lane);
        if (lane == 0) {
            int si = src[ed], di = dst[ed];
            sSrc[e] = si; sDst[e] = di;
            float dx = coords[si * 3 + 0] - coords[di * 3 + 0];
            float dy = coords[si * 3 + 1] - coords[di * 3 + 1];
            float dz = coords[si * 3 + 2] - coords[di * 3 + 2];
            sRad[e] = dx * dx + dy * dy + dz * dz;
            sDx[e] = dx; sDy[e] = dy; sDz[e] = dz;
        }
    }
    __syncthreads();

    const int ecg = tid >> 4;   // rows ecg + 16*i
    const int jcg = tid & 15;   // cols 4jcg..+3, 64+4jcg..+3, 128+2jcg,+1

    // ---- GEMM1-lite: m1 = silu(P1[src] + P2[dst] + [rad,a]@We1[256:273] + be1) ----
    {
        ull acc[4][5];
        #pragma unroll
        for (int i = 0; i < 4; i++) {
            int r = ecg + 16 * i;
            const float* Ps = g_P + (size_t)sSrc[r] * 320;
            const float* Pd = g_P + (size_t)sDst[r] * 320 + 160;
            float4 a0 = __ldg((const float4*)(Ps + 4 * jcg));
            float4 b0 = __ldg((const float4*)(Pd + 4 * jcg));
            acc[i][0] = pk2(a0.x + b0.x, a0.y + b0.y);
            acc[i][1] = pk2(a0.z + b0.z, a0.w + b0.w);
            float4 a1 = __ldg((const float4*)(Ps + 64 + 4 * jcg));
            float4 b1 = __ldg((const float4*)(Pd + 64 + 4 * jcg));
            acc[i][2] = pk2(a1.x + b1.x, a1.y + b1.y);
            acc[i][3] = pk2(a1.z + b1.z, a1.w + b1.w);
            float2 a2 = __ldg((const float2*)(Ps + 128 + 2 * jcg));
            float2 b2 = __ldg((const float2*)(Pd + 128 + 2 * jcg));
            acc[i][4] = pk2(a2.x + b2.x, a2.y + b2.y);
        }
        // k = 0: radial
        {
            const float* wr = We1 + (size_t)256 * INNER;
            float4 w0 = __ldg((const float4*)(wr + 4 * jcg));
            float4 w1 = __ldg((const float4*)(wr + 64 + 4 * jcg));
            float2 w2 = __ldg((const float2*)(wr + 128 + 2 * jcg));
            ull W00 = pk2(w0.x, w0.y), W01 = pk2(w0.z, w0.w);
            ull W10 = pk2(w1.x, w1.y), W11 = pk2(w1.z, w1.w);
            ull W2  = pk2(w2.x, w2.y);
            #pragma unroll
            for (int i = 0; i < 4; i++) {
                float c = sRad[ecg + 16 * i];
                ull fa = pk2(c, c);
                ffma2(acc[i][0], fa, W00); ffma2(acc[i][1], fa, W01);
                ffma2(acc[i][2], fa, W10); ffma2(acc[i][3], fa, W11);
                ffma2(acc[i][4], fa, W2);
            }
        }
        // k = 1..16: edge attrs
        #pragma unroll 4
        for (int k = 0; k < 16; k++) {
            const float* wr = We1 + (size_t)(257 + k) * INNER;
            float4 w0 = __ldg((const float4*)(wr + 4 * jcg));
            float4 w1 = __ldg((const float4*)(wr + 64 + 4 * jcg));
            float2 w2 = __ldg((const float2*)(wr + 128 + 2 * jcg));
            ull W00 = pk2(w0.x, w0.y), W01 = pk2(w0.z, w0.w);
            ull W10 = pk2(w1.x, w1.y), W11 = pk2(w1.z, w1.w);
            ull W2  = pk2(w2.x, w2.y);
            #pragma unroll
            for (int i = 0; i < 4; i++) {
                float c = sA[(ecg + 16 * i) * 16 + k];
                ull fa = pk2(c, c);
                ffma2(acc[i][0], fa, W00); ffma2(acc[i][1], fa, W01);
                ffma2(acc[i][2], fa, W10); ffma2(acc[i][3], fa, W11);
                ffma2(acc[i][4], fa, W2);
            }
        }
        #pragma unroll
        for (int i = 0; i < 4; i++) {
            float* orow = sm1 + (ecg + 16 * i) * 164;
            float lo, hi;
            int c = 4 * jcg;
            upk2(acc[i][0], lo, hi);
            orow[c]   = siluf(lo + __ldg(be1 + c));     orow[c+1] = siluf(hi + __ldg(be1 + c + 1));
            upk2(acc[i][1], lo, hi);
            orow[c+2] = siluf(lo + __ldg(be1 + c + 2)); orow[c+3] = siluf(hi + __ldg(be1 + c + 3));
            c = 64 + 4 * jcg;
            upk2(acc[i][2], lo, hi);
            orow[c]   = siluf(lo + __ldg(be1 + c));     orow[c+1] = siluf(hi + __ldg(be1 + c + 1));
            upk2(acc[i][3], lo, hi);
            orow[c+2] = siluf(lo + __ldg(be1 + c + 2)); orow[c+3] = siluf(hi + __ldg(be1 + c + 3));
            c = 128 + 2 * jcg;
            upk2(acc[i][4], lo, hi);
            orow[c]   = siluf(lo + __ldg(be1 + c));     orow[c+1] = siluf(hi + __ldg(be1 + c + 1));
        }
    }
    __syncthreads();

    // ---- GEMM2 (in-place): m = silu(m1 @ We2 + be2), output overwrites sm1 ----
    {
        ull acc[4][5];
        #pragma unroll
        for (int i = 0; i < 4; i++) { acc[i][0]=0; acc[i][1]=0; acc[i][2]=0; acc[i][3]=0; acc[i][4]=0; }
        const float* f0 = sm1 + (ecg +  0) * 164;
        const float* f1 = sm1 + (ecg + 16) * 164;
        const float* f2p = sm1 + (ecg + 32) * 164;
        const float* f3p = sm1 + (ecg + 48) * 164;
        #pragma unroll 2
        for (int k2 = 0; k2 < INNER; k2 += 2) {
            float2 a0 = *(const float2*)(f0 + k2);
            float2 a1 = *(const float2*)(f1 + k2);
            float2 a2 = *(const float2*)(f2p + k2);
            float2 a3 = *(const float2*)(f3p + k2);
            #pragma unroll
            for (int kk = 0; kk < 2; kk++) {
                ull fa[4];
                float c0 = kk ? a0.y : a0.x, c1 = kk ? a1.y : a1.x;
                float c2 = kk ? a2.y : a2.x, c3 = kk ? a3.y : a3.x;
                fa[0] = pk2(c0, c0); fa[1] = pk2(c1, c1);
                fa[2] = pk2(c2, c2); fa[3] = pk2(c3, c3);
                const float* wr = We2 + (size_t)(k2 + kk) * INNER;
                float4 w0 = __ldg((const float4*)(wr + 4 * jcg));
                float4 w1 = __ldg((const float4*)(wr + 64 + 4 * jcg));
                float2 w2 = __ldg((const float2*)(wr + 128 + 2 * jcg));
                ull W00 = pk2(w0.x, w0.y), W01 = pk2(w0.z, w0.w);
                ull W10 = pk2(w1.x, w1.y), W11 = pk2(w1.z, w1.w);
                ull W2  = pk2(w2.x, w2.y);
                #pragma unroll
                for (int i = 0; i < 4; i++) {
                    ffma2(acc[i][0], fa[i], W00); ffma2(acc[i][1], fa[i], W01);
                    ffma2(acc[i][2], fa[i], W10); ffma2(acc[i][3], fa[i], W11);
                    ffma2(acc[i][4], fa[i], W2);
                }
            }
        }
        __syncthreads();   // all reads of m1 done before in-place overwrite
        #pragma unroll
        for (int i = 0; i < 4; i++) {
            float* orow = sm1 + (ecg + 16 * i) * 164;
            float lo, hi;
            int c = 4 * jcg;
            upk2(acc[i][0], lo, hi);
            orow[c]   = siluf(lo + __ldg(be2 + c));     orow[c+1] = siluf(hi + __ldg(be2 + c + 1));
            upk2(acc[i][1], lo, hi);
            orow[c+2] = siluf(lo + __ldg(be2 + c + 2)); orow[c+3] = siluf(hi + __ldg(be2 + c + 3));
            c = 64 + 4 * jcg;
            upk2(acc[i][2], lo, hi);
            orow[c]   = siluf(lo + __ldg(be2 + c));     orow[c+1] = siluf(hi + __ldg(be2 + c + 1));
            upk2(acc[i][3], lo, hi);
            orow[c+2] = siluf(lo + __ldg(be2 + c + 2)); orow[c+3] = siluf(hi + __ldg(be2 + c + 3));
            c = 128 + 2 * jcg;
            upk2(acc[i][4], lo, hi);
            orow[c]   = siluf(lo + __ldg(be2 + c));     orow[c+1] = siluf(hi + __ldg(be2 + c + 1));
        }
    }
    __syncthreads();

    // ---- logits = m @ Wa ----
    #pragma unroll
    for (int pass = 0; pass < 2; pass++) {
        int e = (tid >> 3) + 32 * pass;
        int hh = tid & 7;
        const float* mr = sm1 + e * 164;
        float accl = 0.f;
        #pragma unroll 8
        for (int k = 0; k < INNER; k++) accl += mr[k] * __ldg(Wa + k * 8 + hh);
        int ed = eg + e;
        if (ed < E) g_logits[(size_t)ed * 8 + hh] = accl;
    }

    // ---- coordinate messages ----
    if (tid < EB) {
        int e = tid;
        const float* mr = sm1 + e * 164;
        float c = 0.f;
        #pragma unroll 8
        for (int k = 0; k < INNER; k++) c += mr[k] * __ldg(Wc + k);
        float s = c / (sqrtf(sRad[e] + 1e-5f) + 1.0f);
        int ed = eg + e;
        if (ed < E) {
            g_msgx[(size_t)ed * 3 + 0] = sDx[e] * s;
            g_msgx[(size_t)ed * 3 + 1] = sDy[e] * s;
            g_msgx[(size_t)ed * 3 + 2] = sDz[e] * s;
        }
    }

    // ---- write m to global ----
    for (int idx = tid; idx < 64 * 40; idx += 256) {
        int r = idx / 40, c4 = idx % 40;
        int ed = eg + r;
        if (ed < E)
            *(float4*)(g_m + (size_t)ed * 160 + 4 * c4) = *(const float4*)(sm1 + r * 164 + 4 * c4);
    }
}

// ---------------- node-centric aggregation (softmax + per-head m-agg + Wv) ----------------
__global__ void __launch_bounds__(128) k_agg(const float* __restrict__ coords,
                                             const float* __restrict__ Wv,
                                             float* __restrict__ out_coords)
{
    const int n = blockIdx.x, tid = threadIdx.x;
    const int s0 = g_start[n];
    const int deg = g_start[n + 1] - s0;
    __shared__ int sh_e[16];
    __shared__ float sh_w[16][8];
    __shared__ float red[16][8];
    __shared__ float sh_mx[8], sh_den[8];
    __shared__ float sh_m[16][160];
    __shared__ float sh_s[8][164];
    __shared__ float sh_c[16][3];
    const int slot = tid >> 3, h8 = tid & 7;

    // pass 1: per-head max
    float mloc = -3.0e38f;
    for (int c = 0; c < deg; c += 16) {
        int len = min(16, deg - c);
        if (tid < len) sh_e[tid] = g_eid[s0 + c + tid];
        __syncthreads();
        if (slot < len) mloc = fmaxf(mloc, g_logits[(size_t)sh_e[slot] * 8 + h8]);
        __syncthreads();
    }
    red[slot][h8] = mloc;
    __syncthreads();
    for (int o = 8; o > 0; o >>= 1) {
        if (slot < o) red[slot][h8] = fmaxf(red[slot][h8], red[slot + o][h8]);
        __syncthreads();
    }
    if (slot == 0) sh_mx[h8] = red[0][h8];
    __syncthreads();

    // pass 2: denominator
    float dloc = 0.f;
    for (int c = 0; c < deg; c += 16) {
        int len = min(16, deg - c);
        if (tid < len) sh_e[tid] = g_eid[s0 + c + tid];
        __syncthreads();
        if (slot < len) dloc += __expf(g_logits[(size_t)sh_e[slot] * 8 + h8] - sh_mx[h8]);
        __syncthreads();
    }
    red[slot][h8] = dloc;
    __syncthreads();
    for (int o = 8; o > 0; o >>= 1) {
        if (slot < o) red[slot][h8] += red[slot + o][h8];
        __syncthreads();
    }
    if (slot == 0) sh_den[h8] = red[0][h8];
    __syncthreads();

    // pass 3: s[h][k] = sum_e w[e,h] * m_e[k]
    const int hh = tid >> 4;      // 0..7
    const int seg = tid & 15;     // dims seg*10 .. +10
    float acc[10];
    #pragma unroll
    for (int d = 0; d < 10; d++) acc[d] = 0.f;

    for (int c = 0; c < deg; c += 16) {
        int len = min(16, deg - c);
        if (tid < len) sh_e[tid] = g_eid[s0 + c + tid];
        __syncthreads();
        if (slot < len)
            sh_w[slot][h8] = __expf(g_logits[(size_t)sh_e[slot] * 8 + h8] - sh_mx[h8]) / sh_den[h8];
        // stage m rows (len x 160)
        #pragma unroll
        for (int q = 0; q < 5; q++) {
            int f4i = tid + 128 * q;
            int r = f4i / 40, c4 = f4i % 40;
            if (r < len)
                *(float4*)(&sh_m[r][4 * c4]) = __ldg((const float4*)(g_m + (size_t)sh_e[r] * 160 + 4 * c4));
        }
        __syncthreads();
        for (int i = 0; i < len; i++) {
            float w = sh_w[i][hh];
            #pragma unroll
            for (int d = 0; d < 10; d++) acc[d] += sh_m[i][seg * 10 + d] * w;
        }
        __syncthreads();
    }
    #pragma unroll
    for (int d = 0; d < 10; d++) sh_s[hh][seg * 10 + d] = acc[d];
    __syncthreads();

    // epilogue: h_agg[j] = sum_k s[j>>4][k] * Wv[k][j]
    {
        const float* sr = sh_s[tid >> 4];
        float hv = 0.f;
        #pragma unroll 8
        for (int k = 0; k < INNER; k++) hv += sr[k] * __ldg(Wv + k * 128 + tid);
        g_hagg[(size_t)n * 128 + tid] = hv;
    }

    // coord scatter-sum
    if (tid < 48) {
        int i0 = tid / 3, cc = tid % 3;
        float cacc = 0.f;
        for (int i = i0; i < deg; i += 16) cacc += g_msgx[(size_t)g_eid[s0 + i] * 3 + cc];
        sh_c[i0][cc] = cacc;
    }
    __syncthreads();
    if (tid < 3) {
        float cacc = 0.f;
        #pragma unroll
        for (int i = 0; i < 16; i++) cacc += sh_c[i][tid];
        out_coords[n * 3 + tid] = coords[n * 3 + tid] + cacc;
    }
}

// ---------------- batched node GEMM helpers ----------------
template<int K, int NP, int C>
__device__ __forceinline__ void gemm_n(const float* __restrict__ sIn, int is,
                                       const float* __restrict__ W,
                                       ull (&acc)[4][NP][2]) {
    const int tid = threadIdx.x;
    const int ecg = tid >> 5, jcg = tid & 31;
    #pragma unroll
    for (int i = 0; i < 4; i++)
        #pragma unroll
        for (int p = 0; p < NP; p++) { acc[i][p][0] = 0; acc[i][p][1] = 0; }
    for (int k4 = 0; k4 < K; k4 += 4) {
        float4 av[4];
        #pragma unroll
        for (int i = 0; i < 4; i++) av[i] = *(const float4*)(sIn + (ecg + 8 * i) * is + k4);
        #pragma unroll
        for (int kk = 0; kk < 4; kk++) {
            ull fa[4];
            #pragma unroll
            for (int i = 0; i < 4; i++) { float c = getc(av[i], kk); fa[i] = pk2(c, c); }
            const float* wr = W + (k4 + kk) * C + 4 * jcg;
            #pragma unroll
            for (int p = 0; p < NP; p++) {
                if ((C % 128 == 0) || (128 * p + 4 * jcg < C)) {
                    float4 wv = __ldg((const float4*)(wr + 128 * p));
                    ull w0 = pk2(wv.x, wv.y), w1 = pk2(wv.z, wv.w);
                    #pragma unroll
                    for (int i = 0; i < 4; i++) { ffma2(acc[i][p][0], fa[i], w0); ffma2(acc[i][p][1], fa[i], w1); }
                }
            }
        }
    }
}

template<int NP, int C>
__device__ __forceinline__ void store_acc(ull (&acc)[4][NP][2], float* sOut, int os,
                                          const float* bias, bool dosilu) {
    const int tid = threadIdx.x, ecg = tid >> 5, jcg = tid & 31;
    #pragma unroll
    for (int i = 0; i < 4; i++) {
        int r = ecg + 8 * i;
        #pragma unroll
        for (int p = 0; p < NP; p++) {
            int c0 = 128 * p + 4 * jcg;
            if ((C % 128 == 0) || (c0 < C)) {
                float v0, v1, v2, v3;
                upk2(acc[i][p][0], v0, v1); upk2(acc[i][p][1], v2, v3);
                if (bias) {
                    v0 += __ldg(bias + c0); v1 += __ldg(bias + c0 + 1);
                    v2 += __ldg(bias + c0 + 2); v3 += __ldg(bias + c0 + 3);
                }
                if (dosilu) { v0 = siluf(v0); v1 = siluf(v1); v2 = siluf(v2); v3 = siluf(v3); }
                *(float4*)(sOut + r * os + c0) = make_float4(v0, v1, v2, v3);
            }
        }
    }
}

__device__ __forceinline__ void film_store(ull (&acc)[4][2][2], float* sScale, float* sShift,
                                           const float* bias) {
    const int tid = threadIdx.x, ecg = tid >> 5, jcg = tid & 31;
    #pragma unroll
    for (int i = 0; i < 4; i++) {
        int r = ecg + 8 * i;
        int c0 = 4 * jcg;
        float v0, v1, v2, v3;
        upk2(acc[i][0][0], v0, v1); upk2(acc[i][0][1], v2, v3);
        v0 += __ldg(bias + c0); v1 += __ldg(bias + c0 + 1);
        v2 += __ldg(bias + c0 + 2); v3 += __ldg(bias + c0 + 3);
        *(float4*)(sScale + r * 132 + c0) = make_float4(v0, v1, v2, v3);
        upk2(acc[i][1][0], v0, v1); upk2(acc[i][1][1], v2, v3);
        v0 += __ldg(bias + 128 + c0); v1 += __ldg(bias + 128 + c0 + 1);
        v2 += __ldg(bias + 128 + c0 + 2); v3 += __ldg(bias + 128 + c0 + 3);
        *(float4*)(sShift + r * 164 + c0) = make_float4(v0, v1, v2, v3);
    }
}

__device__ __forceinline__ void ln_stats(const float* sX, float* sMu, float* sRs) {
    int w = threadIdx.x >> 5, lane = threadIdx.x & 31;
    #pragma unroll
    for (int rr = 0; rr < 4; rr++) {
        int r = w * 4 + rr;
        float4 v = *(const float4*)(sX + r * 132 + 4 * lane);
        float s = v.x + v.y + v.z + v.w;
        float q = v.x * v.x + v.y * v.y + v.z * v.z + v.w * v.w;
        #pragma unroll
        for (int o = 16; o; o >>= 1) {
            s += __shfl_xor_sync(~0u, s, o);
            q += __shfl_xor_sync(~0u, q, o);
        }
        if (lane == 0) {
            float mu = s * (1.f / 128.f);
            float var = q * (1.f / 128.f) - mu * mu;
            sMu[r] = mu; sRs[r] = rsqrtf(var + 1e-5f);
        }
    }
}

// ---------------- batched node kernel (32 nodes/block) ----------------
__global__ void __launch_bounds__(256, 2) k_node(
    const float* __restrict__ h, const float* __restrict__ res, const float* __restrict__ y,
    const float* __restrict__ Wo,
    const float* __restrict__ Wn1, const float* __restrict__ bn1,
    const float* __restrict__ Wn2, const float* __restrict__ bn2,
    const float* __restrict__ Wf1, const float* __restrict__ bf1,
    const float* __restrict__ Wf2, const float* __restrict__ bf2,
    float* __restrict__ out_h2, float* __restrict__ out_res2, int N)
{
    extern __shared__ float sm_n[];
    float* sA  = sm_n;                 // [32][164]
    float* sB  = sA + 32 * 164;        // [32][132]
    float* sC  = sB + 32 * 132;        // [32][132]
    float* sY  = sC + 32 * 132;        // [32][68]
    float* sMu = sY + 32 * 68;         // [32]
    float* sRs = sMu + 32;             // [32]

    const int nb = blockIdx.x * NB;
    const int tid = threadIdx.x;

    for (int idx = tid; idx < 32 * 128; idx += 256) {
        int r = idx >> 7, c = idx & 127;
        int n = min(nb + r, N - 1);
        sB[r * 132 + c] = g_hagg[(size_t)n * 128 + c];
    }
    for (int idx = tid; idx < 32 * 64; idx += 256) {
        int r = idx >> 6, c = idx & 63;
        int n = min(nb + r, N - 1);
        sY[r * 68 + c] = y[(size_t)n * 64 + c];
    }
    __syncthreads();

    {
        ull acc[4][1][2];
        gemm_n<128, 1, 128>(sB, 132, Wo, acc);
        store_acc<1, 128>(acc, sC, 132, nullptr, false);
    }
    __syncthreads();

    float f2r[16];
    #pragma unroll
    for (int t = 0; t < 16; t++) {
        int idx = tid + 256 * t;
        int r = idx >> 7, c = idx & 127;
        int n = min(nb + r, N - 1);
        float f2v = sC[r * 132 + c];
        f2r[t] = f2v;
        sB[r * 132 + c] = h[(size_t)n * 128 + c] + f2v;
    }
    __syncthreads();
    ln_stats(sB, sMu, sRs);
    __syncthreads();

    {
        ull acc[4][2][2];
        gemm_n<64, 2, 256>(sY, 68, Wf1, acc);
        film_store(acc, sC, sA, bf1);
    }
    __syncthreads();

    #pragma unroll
    for (int t = 0; t < 16; t++) {
        int idx = tid + 256 * t;
        int r = idx >> 7, c = idx & 127;
        float x = sB[r * 132 + c];
        float xn = (x - sMu[r]) * sRs[r];
        sB[r * 132 + c] = xn * (1.f + sC[r * 132 + c]) + sA[r * 164 + c];
    }
    __syncthreads();

    {
        ull acc[4][2][2];
        gemm_n<128, 2, 160>(sB, 132, Wn1, acc);
        store_acc<2, 160>(acc, sA, 164, bn1, true);
    }
    __syncthreads();

    {
        ull acc[4][1][2];
        gemm_n<160, 1, 128>(sA, 164, Wn2, acc);
        store_acc<1, 128>(acc, sC, 132, bn2, false);
    }
    __syncthreads();

    #pragma unroll
    for (int t = 0; t < 16; t++) {
        int idx = tid + 256 * t;
        int r = idx >> 7, c = idx & 127;
        float f3 = sC[r * 132 + c];
        int n = nb + r;
        if (n < N) out_res2[(size_t)n * 128 + c] = res[(size_t)n * 128 + c] + f2r[t] + f3;
        sB[r * 132 + c] += f3;
    }
    __syncthreads();
    ln_stats(sB, sMu, sRs);
    __syncthreads();

    {
        ull acc[4][2][2];
        gemm_n<64, 2, 256>(sY, 68, Wf2, acc);
        film_store(acc, sC, sA, bf2);
    }
    __syncthreads();

    #pragma unroll
    for (int t = 0; t < 16; t++) {
        int idx = tid + 256 * t;
        int r = idx >> 7, c = idx & 127;
        int n = nb + r;
        if (n < N) {
            float xn = (sB[r * 132 + c] - sMu[r]) * sRs[r];
            out_h2[(size_t)n * 128 + c] = xn * (1.f + sC[r * 132 + c]) + sA[r * 164 + c];
        }
    }
}

// ---------------- launch ----------------
extern "C" void kernel_launch(void* const* d_in, const int* in_sizes, int n_in,
                              void* d_out, int out_size) {
    const float* h      = (const float*)d_in[0];
    const float* coords = (const float*)d_in[1];
    const float* a      = (const float*)d_in[2];
    const float* y      = (const float*)d_in[3];
    const float* res    = (const float*)d_in[4];
    const int*   src    = (const int*)d_in[5];
    const int*   dst    = (const int*)d_in[6];
    const float* We1 = (const float*)d_in[7];
    const float* be1 = (const float*)d_in[8];
    const float* We2 = (const float*)d_in[9];
    const float* be2 = (const float*)d_in[10];
    const float* Wc  = (const float*)d_in[11];
    const float* Wv  = (const float*)d_in[12];
    const float* Wa  = (const float*)d_in[13];
    const float* Wo  = (const float*)d_in[14];
    const float* Wn1 = (const float*)d_in[15];
    const float* bn1 = (const float*)d_in[16];
    const float* Wn2 = (const float*)d_in[17];
    const float* bn2 = (const float*)d_in[18];
    const float* Wf1 = (const float*)d_in[19];
    const float* bf1 = (const float*)d_in[20];
    const float* Wf2 = (const float*)d_in[21];
    const float* bf2 = (const float*)d_in[22];

    const int N = in_sizes[0] / HID;
    const int E = in_sizes[5];

    float* out = (float*)d_out;
    float* out_h2 = out;
    float* out_coords = out + (size_t)N * HID;
    float* out_res2 = out + (size_t)N * HID + (size_t)N * 3;

    const int SMEM_E = (64 * 164 + 64 * 16 + 64 * 6) * (int)sizeof(float);
    const int SMEM_N = (32 * 164 + 32 * 132 * 2 + 32 * 68 + 64) * (int)sizeof(float);
    cudaFuncSetAttribute(k_edge, cudaFuncAttributeMaxDynamicSharedMemorySize, SMEM_E);
    cudaFuncSetAttribute(k_node, cudaFuncAttributeMaxDynamicSharedMemorySize, SMEM_N);

    k_zero<<<(N + 255) / 256, 256>>>(N);
    k_deg<<<(E + 255) / 256, 256>>>(dst, E);
    k_pre<<<(N + 31) / 32, 256>>>(h, We1, N);
    // k_edge 4th: the ncu window captures launch #4
    k_edge<<<(E + EB - 1) / EB, 256, SMEM_E>>>(coords, a, src, dst,
                                               We1, be1, We2, be2, Wc, Wa, E);
    k_scan<<<1, 1024>>>(N);
    k_fill<<<(E + 255) / 256, 256>>>(dst, E);
    k_agg<<<N, 128>>>(coords, Wv, out_coords);
    k_node<<<(N + NB - 1) / NB, 256, SMEM_N>>>(h, res, y, Wo, Wn1, bn1, Wn2, bn2,
                                               Wf1, bf1, Wf2, bf2, out_h2, out_res2, N);
}